// round 1
// baseline (speedup 1.0000x reference)
#include <cuda_runtime.h>
#include <math.h>

#define Bn   4
#define Tn   1024
#define Cn   2048
#define Hn   16
#define HDn  128
#define NBLK 1024
#define M_ALL (Bn*Tn)          // 4096
#define N_QKV (3*Cn)           // 6144

// ---------------- scratch (device globals; no runtime allocation) -------------
__device__ float g_qkv[(size_t)M_ALL * N_QKV];      // 100.7 MB
__device__ float g_q[(size_t)Bn*Hn*Tn*HDn];         // 33.5 MB
__device__ float g_k[(size_t)Bn*Hn*Tn*HDn];
__device__ float g_v[(size_t)Bn*Hn*Tn*HDn];
__device__ float g_y[(size_t)M_ALL * Cn];           // 33.5 MB
__device__ float g_t[Bn*Tn];

// ---------------- kernel 1: global histogram + per-batch cumsum ---------------
__global__ void t_kernel(const int* __restrict__ tok) {
    __shared__ int   cnt[NBLK];
    __shared__ float buf[Tn];
    int tid = threadIdx.x;                 // 1024 threads
    cnt[tid] = 0;
    __syncthreads();
    for (int i = tid; i < Bn*Tn; i += blockDim.x)
        atomicAdd(&cnt[tok[i]], 1);
    __syncthreads();
    for (int b = 0; b < Bn; b++) {
        float r = 1.0f / ((float)cnt[tok[b*Tn + tid]] + 1e-10f);
        buf[tid] = r;
        __syncthreads();
        #pragma unroll
        for (int off = 1; off < Tn; off <<= 1) {
            float v = (tid >= off) ? buf[tid - off] : 0.0f;
            __syncthreads();
            buf[tid] += v;
            __syncthreads();
        }
        g_t[b*Tn + tid] = buf[tid];
        __syncthreads();
    }
}

// ---------------- kernel 2: generic fp32 SGEMM (128x128x16, 8x8 microtile) ----
__global__ __launch_bounds__(256)
void sgemm_kernel(const float* __restrict__ A, const float* __restrict__ Bm,
                  float* __restrict__ Cm, int M, int N, int K) {
    __shared__ float As[16][132];
    __shared__ float Bs[16][132];
    int tid = threadIdx.x;
    int row0 = blockIdx.y * 128, col0 = blockIdx.x * 128;
    int tx = tid & 15, ty = tid >> 4;
    float acc[8][8];
    #pragma unroll
    for (int i = 0; i < 8; i++)
        #pragma unroll
        for (int j = 0; j < 8; j++) acc[i][j] = 0.0f;

    for (int k0 = 0; k0 < K; k0 += 16) {
        #pragma unroll
        for (int i = 0; i < 2; i++) {
            int slot = tid + i*256;
            int ar = slot >> 2, ak = (slot & 3) << 2;
            float4 av = *(const float4*)&A[(size_t)(row0+ar)*K + k0 + ak];
            As[ak+0][ar] = av.x; As[ak+1][ar] = av.y;
            As[ak+2][ar] = av.z; As[ak+3][ar] = av.w;
            int br = slot >> 5, bc = (slot & 31) << 2;
            *(float4*)&Bs[br][bc] = *(const float4*)&Bm[(size_t)(k0+br)*N + col0 + bc];
        }
        __syncthreads();
        #pragma unroll
        for (int kk = 0; kk < 16; kk++) {
            float a[8], b[8];
            *(float4*)&a[0] = *(float4*)&As[kk][ty*8];
            *(float4*)&a[4] = *(float4*)&As[kk][ty*8+4];
            *(float4*)&b[0] = *(float4*)&Bs[kk][tx*8];
            *(float4*)&b[4] = *(float4*)&Bs[kk][tx*8+4];
            #pragma unroll
            for (int i = 0; i < 8; i++)
                #pragma unroll
                for (int j = 0; j < 8; j++)
                    acc[i][j] = fmaf(a[i], b[j], acc[i][j]);
        }
        __syncthreads();
    }
    #pragma unroll
    for (int i = 0; i < 8; i++) {
        size_t r = (size_t)(row0 + ty*8 + i) * N + col0 + tx*8;
        float4 v0 = make_float4(acc[i][0], acc[i][1], acc[i][2], acc[i][3]);
        float4 v1 = make_float4(acc[i][4], acc[i][5], acc[i][6], acc[i][7]);
        *(float4*)&Cm[r]     = v0;
        *(float4*)&Cm[r + 4] = v1;
    }
}

// ---------------- kernel 3: RoPE + overrides + head transpose ----------------
__global__ void transform_kernel(const float* __restrict__ cum) {
    int idx = blockIdx.x * blockDim.x + threadIdx.x;   // Bn*Tn*Hn*64
    int j = idx & 63;
    int h = (idx >> 6) & (Hn-1);
    int t = (idx >> 10) & (Tn-1);
    int b = idx >> 20;

    const float* row = g_qkv + (size_t)(b*Tn + t) * N_QKV;
    float tv = g_t[b*Tn + t];
    // inv_freq = 10000^(-j/64), computed in double for fidelity
    float invf = (float)exp(-(double)j * (9.210340371976184 / 64.0));
    float ang = tv * invf;
    float sn, cs_;
    sincosf(ang, &sn, &cs_);

    float q1 = row[h*HDn + j],        q2 = row[h*HDn + j + 64];
    float k1 = row[Cn + h*HDn + j],   k2 = row[Cn + h*HDn + j + 64];
    float v1 = row[2*Cn + h*HDn + j], v2 = row[2*Cn + h*HDn + j + 64];
    float cscore = cum[b*Tn + t];
    float ev = expf(cscore);

    float qo1 = q1*cs_ - q2*sn, qo2 = q2*cs_ + q1*sn;
    float ko1 = k1*cs_ - k2*sn, ko2 = k2*cs_ + k1*sn;
    if (j == 63) { qo2 = 1.0f; ko2 = cscore; }   // overrides at d=127 (post-RoPE)

    size_t base = (((size_t)(b*Hn + h))*Tn + t) * HDn;
    g_q[base + j] = qo1;  g_q[base + j + 64] = qo2;
    g_k[base + j] = ko1;  g_k[base + j + 64] = ko2;
    g_v[base + j] = v1*ev; g_v[base + j + 64] = v2*ev;
}

// ---------------- kernel 4: flash attention, fp32, 64x64 tiles ---------------
#define SQ 132     // padded row stride for Q/K/V tiles (conflict-aware)
#define SP 68      // padded row stride for P tile
#define ATTN_SMEM ((3*64*SQ + 64*SP) * 4)

__global__ __launch_bounds__(128)
void attn_kernel(const int* __restrict__ pad) {
    extern __shared__ float sm[];
    float* Qs = sm;
    float* Ks = Qs + 64*SQ;
    float* Vs = Ks + 64*SQ;
    float* Ps = Vs + 64*SQ;
    __shared__ int pads[64];

    int tid  = threadIdx.x;
    int mtile = blockIdx.x;          // 16 query tiles
    int bh    = blockIdx.y;          // 64 (b,h)
    int b = bh >> 4, h = bh & 15;

    int cq = tid & 7;                // col lane (strided score cols: j*8+cq)
    int rg = tid >> 3;               // row group
    int r0 = rg << 2;                // 4 rows per thread

    // load Q tile (64x128)
    const float* Qg = g_q + ((size_t)bh*Tn + mtile*64) * HDn;
    #pragma unroll
    for (int i = 0; i < 16; i++) {
        int slot = tid + i*128;
        int r = slot >> 5, c4 = (slot & 31) << 2;
        *(float4*)&Qs[r*SQ + c4] = *(const float4*)&Qg[r*HDn + c4];
    }

    float m[4], l[4], acc[4][16];
    #pragma unroll
    for (int i = 0; i < 4; i++) {
        m[i] = -3.0e38f; l[i] = 0.0f;
        #pragma unroll
        for (int t = 0; t < 16; t++) acc[i][t] = 0.0f;
    }
    const float SCALE = 0.08838834764831843f;   // 1/sqrt(128)

    for (int n = 0; n <= mtile; n++) {
        __syncthreads();   // previous-iter consumers done (also covers Q store)
        const float* Kg = g_k + ((size_t)bh*Tn + n*64) * HDn;
        const float* Vg = g_v + ((size_t)bh*Tn + n*64) * HDn;
        #pragma unroll
        for (int i = 0; i < 16; i++) {
            int slot = tid + i*128;
            int r = slot >> 5, c4 = (slot & 31) << 2;
            *(float4*)&Ks[r*SQ + c4] = *(const float4*)&Kg[r*HDn + c4];
            *(float4*)&Vs[r*SQ + c4] = *(const float4*)&Vg[r*HDn + c4];
        }
        if (tid < 64) pads[tid] = pad[b*Tn + n*64 + tid];
        __syncthreads();

        // S = Q Kᵀ  (s[i][j] -> row r0+i, col j*8+cq)
        float s[4][8];
        #pragma unroll
        for (int i = 0; i < 4; i++)
            #pragma unroll
            for (int j = 0; j < 8; j++) s[i][j] = 0.0f;
        for (int kk = 0; kk < 128; kk += 4) {
            float4 aq[4], bk[8];
            #pragma unroll
            for (int i = 0; i < 4; i++) aq[i] = *(float4*)&Qs[(r0+i)*SQ + kk];
            #pragma unroll
            for (int j = 0; j < 8; j++) bk[j] = *(float4*)&Ks[((j<<3)+cq)*SQ + kk];
            #pragma unroll
            for (int i = 0; i < 4; i++)
                #pragma unroll
                for (int j = 0; j < 8; j++) {
                    s[i][j] = fmaf(aq[i].x, bk[j].x, s[i][j]);
                    s[i][j] = fmaf(aq[i].y, bk[j].y, s[i][j]);
                    s[i][j] = fmaf(aq[i].z, bk[j].z, s[i][j]);
                    s[i][j] = fmaf(aq[i].w, bk[j].w, s[i][j]);
                }
        }
        // scale + causal/padding mask
        #pragma unroll
        for (int i = 0; i < 4; i++) {
            int qg = mtile*64 + r0 + i;
            #pragma unroll
            for (int j = 0; j < 8; j++) {
                int col = (j<<3) + cq;
                int kg = n*64 + col;
                float val = s[i][j] * SCALE;
                if (kg > qg || pads[col] == 0) val = -1.0e30f;
                s[i][j] = val;
            }
        }
        // online softmax update
        #pragma unroll
        for (int i = 0; i < 4; i++) {
            float mx = s[i][0];
            #pragma unroll
            for (int j = 1; j < 8; j++) mx = fmaxf(mx, s[i][j]);
            mx = fmaxf(mx, __shfl_xor_sync(0xffffffffu, mx, 1, 8));
            mx = fmaxf(mx, __shfl_xor_sync(0xffffffffu, mx, 2, 8));
            mx = fmaxf(mx, __shfl_xor_sync(0xffffffffu, mx, 4, 8));
            float mn = fmaxf(m[i], mx);
            float alpha = __expf(m[i] - mn);
            float ls = 0.0f;
            #pragma unroll
            for (int j = 0; j < 8; j++) {
                float p = __expf(s[i][j] - mn);
                s[i][j] = p;
                ls += p;
            }
            ls += __shfl_xor_sync(0xffffffffu, ls, 1, 8);
            ls += __shfl_xor_sync(0xffffffffu, ls, 2, 8);
            ls += __shfl_xor_sync(0xffffffffu, ls, 4, 8);
            l[i] = l[i]*alpha + ls;
            m[i] = mn;
            #pragma unroll
            for (int t = 0; t < 16; t++) acc[i][t] *= alpha;
            #pragma unroll
            for (int j = 0; j < 8; j++) Ps[(r0+i)*SP + (j<<3) + cq] = s[i][j];
        }
        __syncthreads();

        // O += P V   (acc[i][q*4+u] -> col cq*4 + q*32 + u)
        for (int kk = 0; kk < 64; kk += 4) {
            float4 ap[4];
            #pragma unroll
            for (int i = 0; i < 4; i++) ap[i] = *(float4*)&Ps[(r0+i)*SP + kk];
            #pragma unroll
            for (int u = 0; u < 4; u++) {
                float4 bv[4];
                #pragma unroll
                for (int q = 0; q < 4; q++)
                    bv[q] = *(float4*)&Vs[(kk+u)*SQ + cq*4 + q*32];
                #pragma unroll
                for (int i = 0; i < 4; i++) {
                    float a = (u==0) ? ap[i].x : (u==1) ? ap[i].y : (u==2) ? ap[i].z : ap[i].w;
                    #pragma unroll
                    for (int q = 0; q < 4; q++) {
                        acc[i][q*4+0] = fmaf(a, bv[q].x, acc[i][q*4+0]);
                        acc[i][q*4+1] = fmaf(a, bv[q].y, acc[i][q*4+1]);
                        acc[i][q*4+2] = fmaf(a, bv[q].z, acc[i][q*4+2]);
                        acc[i][q*4+3] = fmaf(a, bv[q].w, acc[i][q*4+3]);
                    }
                }
            }
        }
    }
    // epilogue: normalize and write y in [B,T,C] layout
    #pragma unroll
    for (int i = 0; i < 4; i++) {
        float inv = 1.0f / l[i];
        size_t rbase = (size_t)(b*Tn + mtile*64 + r0 + i) * Cn + h*HDn;
        #pragma unroll
        for (int q = 0; q < 4; q++) {
            float4 o = make_float4(acc[i][q*4+0]*inv, acc[i][q*4+1]*inv,
                                   acc[i][q*4+2]*inv, acc[i][q*4+3]*inv);
            *(float4*)&g_y[rbase + cq*4 + q*32] = o;
        }
    }
}

// ---------------- launcher ----------------------------------------------------
extern "C" void kernel_launch(void* const* d_in, const int* in_sizes, int n_in,
                              void* d_out, int out_size) {
    const float* x    = (const float*)d_in[0];
    const float* cum  = (const float*)d_in[1];
    const int*   tok  = (const int*)d_in[2];
    const int*   padm = (const int*)d_in[3];
    const float* Wa   = (const float*)d_in[4];
    const float* Wp   = (const float*)d_in[5];
    float* out = (float*)d_out;

    float *qkv_p, *y_p;
    cudaGetSymbolAddress((void**)&qkv_p, g_qkv);
    cudaGetSymbolAddress((void**)&y_p,   g_y);

    cudaFuncSetAttribute(attn_kernel,
                         cudaFuncAttributeMaxDynamicSharedMemorySize, ATTN_SMEM);

    t_kernel<<<1, 1024>>>(tok);
    sgemm_kernel<<<dim3(N_QKV/128, M_ALL/128), 256>>>(x, Wa, qkv_p, M_ALL, N_QKV, Cn);
    transform_kernel<<<(Bn*Tn*Hn*64)/256, 256>>>(cum);
    attn_kernel<<<dim3(Tn/64, Bn*Hn), 128, ATTN_SMEM>>>(padm);
    sgemm_kernel<<<dim3(Cn/128, M_ALL/128), 256>>>(y_p, Wp, out, M_ALL, Cn, Cn);
}

// round 3
// speedup vs baseline: 2.0416x; 2.0416x over previous
#include <cuda_runtime.h>
#include <cuda_bf16.h>
#include <cstdint>
#include <math.h>

#define Bn   4
#define Tn   1024
#define Cn   2048
#define Hn   16
#define HDn  128
#define NBLK 1024
#define M_ALL (Bn*Tn)          // 4096
#define N_QKV (3*Cn)           // 6144

// ---------------- scratch (device globals; no runtime allocation) -------------
__device__ float g_qkv[(size_t)M_ALL * N_QKV];      // 100.7 MB
__device__ float g_q[(size_t)Bn*Hn*Tn*HDn];
__device__ float g_k[(size_t)Bn*Hn*Tn*HDn];
__device__ float g_v[(size_t)Bn*Hn*Tn*HDn];
__device__ float g_y[(size_t)M_ALL * Cn];
__device__ float g_t[Bn*Tn];
// bf16 split scratch
__device__ __nv_bfloat16 g_xhi[(size_t)M_ALL*Cn],  g_xlo[(size_t)M_ALL*Cn];
__device__ __nv_bfloat16 g_Wahi[(size_t)Cn*N_QKV], g_Walo[(size_t)Cn*N_QKV];
__device__ __nv_bfloat16 g_Wphi[(size_t)Cn*Cn],    g_Wplo[(size_t)Cn*Cn];
__device__ __nv_bfloat16 g_yhi[(size_t)M_ALL*Cn],  g_ylo[(size_t)M_ALL*Cn];

__device__ __forceinline__ uint32_t smem_u32(const void* p) {
    uint32_t a;
    asm("{ .reg .u64 t; cvta.to.shared.u64 t, %1; cvt.u32.u64 %0, t; }"
        : "=r"(a) : "l"(p));
    return a;
}
#define CP_ASYNC16(sa, gp) \
    asm volatile("cp.async.cg.shared.global [%0], [%1], 16;" :: "r"(sa), "l"(gp))
#define CP_COMMIT() asm volatile("cp.async.commit_group;" ::: "memory")
#define CP_WAIT(n)  asm volatile("cp.async.wait_group %0;" :: "n"(n) : "memory")

// ---------------- split kernel: f32 -> bf16 hi + bf16 lo ----------------------
__global__ void split_kernel(const float* __restrict__ src,
                             __nv_bfloat16* __restrict__ hi,
                             __nv_bfloat16* __restrict__ lo, int n4) {
    int i = blockIdx.x * blockDim.x + threadIdx.x;
    if (i >= n4) return;
    float4 v = ((const float4*)src)[i];
    float xs[4] = {v.x, v.y, v.z, v.w};
    __nv_bfloat16 h[4], l[4];
    #pragma unroll
    for (int j = 0; j < 4; j++) {
        h[j] = __float2bfloat16_rn(xs[j]);
        l[j] = __float2bfloat16_rn(xs[j] - __bfloat162float(h[j]));
    }
    ((uint2*)hi)[i] = *(uint2*)h;
    ((uint2*)lo)[i] = *(uint2*)l;
}

// ==================== HMMA bf16-split GEMM ====================================
// C[M,N] = (Ah+Al)[M,K] * (Bh+Bl)[K,N], fp32 accum, 3 terms (hh, hl, lh).
// Tiles: BM=128, BN=128, BK=32. 256 threads (8 warps), warp tile 64x32.
// 4-stage cp.async pipeline. smem/stage = 32KB (Ah 8K | Al 8K | Bh 8K | Bl 8K).
#define ST_BYTES 32768
#define OFF_AL   8192
#define OFF_BH   16384
#define OFF_BL   24576
#define GEMM_SMEM (4*ST_BYTES)

__device__ __forceinline__ void issue_stage(
        const __nv_bfloat16* __restrict__ Ah, const __nv_bfloat16* __restrict__ Al,
        const __nv_bfloat16* __restrict__ Bh, const __nv_bfloat16* __restrict__ Bl,
        int K, int N, int m0, int n0, int k0, uint32_t st, int tid) {
    #pragma unroll
    for (int i = 0; i < 2; i++) {
        int g = tid + i*256;               // 0..511
        int m = g >> 2, c = g & 3;         // A: 128 rows x 4 chunks(16B)
        size_t ga = (size_t)(m0 + m)*K + k0 + c*8;
        uint32_t sa = st + m*64 + (((uint32_t)c ^ ((m>>1)&3)) << 4);
        CP_ASYNC16(sa,          Ah + ga);
        CP_ASYNC16(sa + OFF_AL, Al + ga);
        int k = g >> 4, cn = g & 15;       // B: 32 rows x 16 chunks
        size_t gb = (size_t)(k0 + k)*N + n0 + cn*8;
        uint32_t sb = st + OFF_BH + k*256 + (((uint32_t)cn ^ (k&7)) << 4);
        CP_ASYNC16(sb,          Bh + gb);
        CP_ASYNC16(sb + 8192,   Bl + gb);
    }
}

__device__ __forceinline__ void ldm_a(uint32_t base, int rowbase, int s,
                                      uint32_t* f, int lane) {
    int row = rowbase + (lane & 7) + 8*((lane>>3)&1);
    int ch  = 2*s + (lane>>4);
    uint32_t a = base + row*64 + (((uint32_t)ch ^ ((row>>1)&3)) << 4);
    asm volatile("ldmatrix.sync.aligned.m8n8.x4.shared.b16 {%0,%1,%2,%3}, [%4];"
                 : "=r"(f[0]), "=r"(f[1]), "=r"(f[2]), "=r"(f[3]) : "r"(a));
}
__device__ __forceinline__ void ldm_b(uint32_t base, int s, int cb,
                                      uint32_t* f, int lane) {
    int k  = 16*s + (lane & 7) + 8*((lane>>3)&1);
    int ch = cb + (lane>>4);
    uint32_t a = base + k*256 + (((uint32_t)ch ^ (k&7)) << 4);
    asm volatile("ldmatrix.sync.aligned.m8n8.x4.trans.shared.b16 {%0,%1,%2,%3}, [%4];"
                 : "=r"(f[0]), "=r"(f[1]), "=r"(f[2]), "=r"(f[3]) : "r"(a));
}
#define MMA(cp, a, b0, b1) \
    asm volatile("mma.sync.aligned.m16n8k16.row.col.f32.bf16.bf16.f32 " \
        "{%0,%1,%2,%3}, {%4,%5,%6,%7}, {%8,%9}, {%0,%1,%2,%3};" \
        : "+f"((cp)[0]), "+f"((cp)[1]), "+f"((cp)[2]), "+f"((cp)[3]) \
        : "r"((a)[0]), "r"((a)[1]), "r"((a)[2]), "r"((a)[3]), "r"(b0), "r"(b1))

__global__ __launch_bounds__(256, 1)
void hmma_gemm(const __nv_bfloat16* __restrict__ Ah, const __nv_bfloat16* __restrict__ Al,
               const __nv_bfloat16* __restrict__ Bh, const __nv_bfloat16* __restrict__ Bl,
               float* __restrict__ Cg, int M, int N, int K) {
    extern __shared__ char smraw[];
    uint32_t sb = smem_u32(smraw);
    int tid = threadIdx.x;
    int lane = tid & 31, warp = tid >> 5;
    int wm = warp >> 2, wn = warp & 3;     // warp tile: rows wm*64, cols wn*32
    int m0 = blockIdx.y * 128, n0 = blockIdx.x * 128;

    float acc[4][4][4];
    #pragma unroll
    for (int a = 0; a < 4; a++)
        #pragma unroll
        for (int b = 0; b < 4; b++)
            #pragma unroll
            for (int c = 0; c < 4; c++) acc[a][b][c] = 0.0f;

    const int NK = K / 32;
    #pragma unroll
    for (int p = 0; p < 3; p++) {
        issue_stage(Ah, Al, Bh, Bl, K, N, m0, n0, p*32, sb + p*ST_BYTES, tid);
        CP_COMMIT();
    }

    for (int kt = 0; kt < NK; kt++) {
        CP_WAIT(2);
        __syncthreads();
        uint32_t st = sb + (kt & 3)*ST_BYTES;
        #pragma unroll
        for (int s = 0; s < 2; s++) {
            uint32_t af[4][4], alf[4][4], bf[2][4], blf[2][4];
            #pragma unroll
            for (int mi = 0; mi < 4; mi++) {
                ldm_a(st,          wm*64 + mi*16, s, af[mi],  lane);
                ldm_a(st + OFF_AL, wm*64 + mi*16, s, alf[mi], lane);
            }
            #pragma unroll
            for (int nj = 0; nj < 2; nj++) {
                ldm_b(st + OFF_BH, s, wn*4 + nj*2, bf[nj],  lane);
                ldm_b(st + OFF_BL, s, wn*4 + nj*2, blf[nj], lane);
            }
            #pragma unroll
            for (int mi = 0; mi < 4; mi++)
                #pragma unroll
                for (int ni = 0; ni < 4; ni++) {
                    int nj = ni >> 1, o = (ni & 1) << 1;
                    MMA(acc[mi][ni], af[mi],  bf[nj][o],  bf[nj][o+1]);
                    MMA(acc[mi][ni], af[mi],  blf[nj][o], blf[nj][o+1]);
                    MMA(acc[mi][ni], alf[mi], bf[nj][o],  bf[nj][o+1]);
                }
        }
        if (kt + 3 < NK)
            issue_stage(Ah, Al, Bh, Bl, K, N, m0, n0, (kt+3)*32,
                        sb + ((kt+3) & 3)*ST_BYTES, tid);
        CP_COMMIT();
    }

    // epilogue
    int rq = lane >> 2, cq = (lane & 3) << 1;
    #pragma unroll
    for (int mi = 0; mi < 4; mi++) {
        int r = m0 + wm*64 + mi*16 + rq;
        #pragma unroll
        for (int ni = 0; ni < 4; ni++) {
            int cc = n0 + wn*32 + ni*8 + cq;
            *(float2*)&Cg[(size_t)r*N + cc] =
                make_float2(acc[mi][ni][0], acc[mi][ni][1]);
            *(float2*)&Cg[(size_t)(r+8)*N + cc] =
                make_float2(acc[mi][ni][2], acc[mi][ni][3]);
        }
    }
}

// ---------------- kernel 1: global histogram + per-batch cumsum ---------------
__global__ void t_kernel(const int* __restrict__ tok) {
    __shared__ int   cnt[NBLK];
    __shared__ float buf[Tn];
    int tid = threadIdx.x;
    cnt[tid] = 0;
    __syncthreads();
    for (int i = tid; i < Bn*Tn; i += blockDim.x)
        atomicAdd(&cnt[tok[i]], 1);
    __syncthreads();
    for (int b = 0; b < Bn; b++) {
        float r = 1.0f / ((float)cnt[tok[b*Tn + tid]] + 1e-10f);
        buf[tid] = r;
        __syncthreads();
        #pragma unroll
        for (int off = 1; off < Tn; off <<= 1) {
            float v = (tid >= off) ? buf[tid - off] : 0.0f;
            __syncthreads();
            buf[tid] += v;
            __syncthreads();
        }
        g_t[b*Tn + tid] = buf[tid];
        __syncthreads();
    }
}

// ---------------- kernel 3: RoPE + overrides + head transpose ----------------
__global__ void transform_kernel(const float* __restrict__ cum) {
    int idx = blockIdx.x * blockDim.x + threadIdx.x;
    int j = idx & 63;
    int h = (idx >> 6) & (Hn-1);
    int t = (idx >> 10) & (Tn-1);
    int b = idx >> 20;

    const float* row = g_qkv + (size_t)(b*Tn + t) * N_QKV;
    float tv = g_t[b*Tn + t];
    float invf = (float)exp(-(double)j * (9.210340371976184 / 64.0));
    float ang = tv * invf;
    float sn, cs_;
    sincosf(ang, &sn, &cs_);

    float q1 = row[h*HDn + j],        q2 = row[h*HDn + j + 64];
    float k1 = row[Cn + h*HDn + j],   k2 = row[Cn + h*HDn + j + 64];
    float v1 = row[2*Cn + h*HDn + j], v2 = row[2*Cn + h*HDn + j + 64];
    float cscore = cum[b*Tn + t];
    float ev = expf(cscore);

    float qo1 = q1*cs_ - q2*sn, qo2 = q2*cs_ + q1*sn;
    float ko1 = k1*cs_ - k2*sn, ko2 = k2*cs_ + k1*sn;
    if (j == 63) { qo2 = 1.0f; ko2 = cscore; }

    size_t base = (((size_t)(b*Hn + h))*Tn + t) * HDn;
    g_q[base + j] = qo1;  g_q[base + j + 64] = qo2;
    g_k[base + j] = ko1;  g_k[base + j + 64] = ko2;
    g_v[base + j] = v1*ev; g_v[base + j + 64] = v2*ev;
}

// ---------------- kernel 4: flash attention, fp32, 64x64 tiles ---------------
#define SQ 132
#define SP 68
#define ATTN_SMEM ((3*64*SQ + 64*SP) * 4)

__global__ __launch_bounds__(128)
void attn_kernel(const int* __restrict__ pad) {
    extern __shared__ float smf[];
    float* Qs = smf;
    float* Ks = Qs + 64*SQ;
    float* Vs = Ks + 64*SQ;
    float* Ps = Vs + 64*SQ;
    __shared__ int pads[64];

    int tid  = threadIdx.x;
    int mtile = blockIdx.x;
    int bh    = blockIdx.y;
    int b = bh >> 4, h = bh & 15;

    int cq = tid & 7;
    int rg = tid >> 3;
    int r0 = rg << 2;

    const float* Qg = g_q + ((size_t)bh*Tn + mtile*64) * HDn;
    #pragma unroll
    for (int i = 0; i < 16; i++) {
        int slot = tid + i*128;
        int r = slot >> 5, c4 = (slot & 31) << 2;
        *(float4*)&Qs[r*SQ + c4] = *(const float4*)&Qg[r*HDn + c4];
    }

    float m[4], l[4], acc[4][16];
    #pragma unroll
    for (int i = 0; i < 4; i++) {
        m[i] = -3.0e38f; l[i] = 0.0f;
        #pragma unroll
        for (int t = 0; t < 16; t++) acc[i][t] = 0.0f;
    }
    const float SCALE = 0.08838834764831843f;

    for (int n = 0; n <= mtile; n++) {
        __syncthreads();
        const float* Kg = g_k + ((size_t)bh*Tn + n*64) * HDn;
        const float* Vg = g_v + ((size_t)bh*Tn + n*64) * HDn;
        #pragma unroll
        for (int i = 0; i < 16; i++) {
            int slot = tid + i*128;
            int r = slot >> 5, c4 = (slot & 31) << 2;
            *(float4*)&Ks[r*SQ + c4] = *(const float4*)&Kg[r*HDn + c4];
            *(float4*)&Vs[r*SQ + c4] = *(const float4*)&Vg[r*HDn + c4];
        }
        if (tid < 64) pads[tid] = pad[b*Tn + n*64 + tid];
        __syncthreads();

        float s[4][8];
        #pragma unroll
        for (int i = 0; i < 4; i++)
            #pragma unroll
            for (int j = 0; j < 8; j++) s[i][j] = 0.0f;
        for (int kk = 0; kk < 128; kk += 4) {
            float4 aq[4], bk[8];
            #pragma unroll
            for (int i = 0; i < 4; i++) aq[i] = *(float4*)&Qs[(r0+i)*SQ + kk];
            #pragma unroll
            for (int j = 0; j < 8; j++) bk[j] = *(float4*)&Ks[((j<<3)+cq)*SQ + kk];
            #pragma unroll
            for (int i = 0; i < 4; i++)
                #pragma unroll
                for (int j = 0; j < 8; j++) {
                    s[i][j] = fmaf(aq[i].x, bk[j].x, s[i][j]);
                    s[i][j] = fmaf(aq[i].y, bk[j].y, s[i][j]);
                    s[i][j] = fmaf(aq[i].z, bk[j].z, s[i][j]);
                    s[i][j] = fmaf(aq[i].w, bk[j].w, s[i][j]);
                }
        }
        #pragma unroll
        for (int i = 0; i < 4; i++) {
            int qg = mtile*64 + r0 + i;
            #pragma unroll
            for (int j = 0; j < 8; j++) {
                int col = (j<<3) + cq;
                int kg = n*64 + col;
                float val = s[i][j] * SCALE;
                if (kg > qg || pads[col] == 0) val = -1.0e30f;
                s[i][j] = val;
            }
        }
        #pragma unroll
        for (int i = 0; i < 4; i++) {
            float mx = s[i][0];
            #pragma unroll
            for (int j = 1; j < 8; j++) mx = fmaxf(mx, s[i][j]);
            mx = fmaxf(mx, __shfl_xor_sync(0xffffffffu, mx, 1, 8));
            mx = fmaxf(mx, __shfl_xor_sync(0xffffffffu, mx, 2, 8));
            mx = fmaxf(mx, __shfl_xor_sync(0xffffffffu, mx, 4, 8));
            float mn = fmaxf(m[i], mx);
            float alpha = __expf(m[i] - mn);
            float ls = 0.0f;
            #pragma unroll
            for (int j = 0; j < 8; j++) {
                float p = __expf(s[i][j] - mn);
                s[i][j] = p;
                ls += p;
            }
            ls += __shfl_xor_sync(0xffffffffu, ls, 1, 8);
            ls += __shfl_xor_sync(0xffffffffu, ls, 2, 8);
            ls += __shfl_xor_sync(0xffffffffu, ls, 4, 8);
            l[i] = l[i]*alpha + ls;
            m[i] = mn;
            #pragma unroll
            for (int t = 0; t < 16; t++) acc[i][t] *= alpha;
            #pragma unroll
            for (int j = 0; j < 8; j++) Ps[(r0+i)*SP + (j<<3) + cq] = s[i][j];
        }
        __syncthreads();

        for (int kk = 0; kk < 64; kk += 4) {
            float4 ap[4];
            #pragma unroll
            for (int i = 0; i < 4; i++) ap[i] = *(float4*)&Ps[(r0+i)*SP + kk];
            #pragma unroll
            for (int u = 0; u < 4; u++) {
                float4 bv[4];
                #pragma unroll
                for (int q = 0; q < 4; q++)
                    bv[q] = *(float4*)&Vs[(kk+u)*SQ + cq*4 + q*32];
                #pragma unroll
                for (int i = 0; i < 4; i++) {
                    float a = (u==0) ? ap[i].x : (u==1) ? ap[i].y : (u==2) ? ap[i].z : ap[i].w;
                    #pragma unroll
                    for (int q = 0; q < 4; q++) {
                        acc[i][q*4+0] = fmaf(a, bv[q].x, acc[i][q*4+0]);
                        acc[i][q*4+1] = fmaf(a, bv[q].y, acc[i][q*4+1]);
                        acc[i][q*4+2] = fmaf(a, bv[q].z, acc[i][q*4+2]);
                        acc[i][q*4+3] = fmaf(a, bv[q].w, acc[i][q*4+3]);
                    }
                }
            }
        }
    }
    #pragma unroll
    for (int i = 0; i < 4; i++) {
        float inv = 1.0f / l[i];
        size_t rbase = (size_t)(b*Tn + mtile*64 + r0 + i) * Cn + h*HDn;
        #pragma unroll
        for (int q = 0; q < 4; q++) {
            float4 o = make_float4(acc[i][q*4+0]*inv, acc[i][q*4+1]*inv,
                                   acc[i][q*4+2]*inv, acc[i][q*4+3]*inv);
            *(float4*)&g_y[rbase + cq*4 + q*32] = o;
        }
    }
}

// ---------------- launcher ----------------------------------------------------
extern "C" void kernel_launch(void* const* d_in, const int* in_sizes, int n_in,
                              void* d_out, int out_size) {
    const float* x    = (const float*)d_in[0];
    const float* cum  = (const float*)d_in[1];
    const int*   tok  = (const int*)d_in[2];
    const int*   padm = (const int*)d_in[3];
    const float* Wa   = (const float*)d_in[4];
    const float* Wp   = (const float*)d_in[5];
    float* out = (float*)d_out;

    float *qkv_p, *y_p;
    __nv_bfloat16 *xhi, *xlo, *wahi, *walo, *wphi, *wplo, *yhi, *ylo;
    cudaGetSymbolAddress((void**)&qkv_p, g_qkv);
    cudaGetSymbolAddress((void**)&y_p,   g_y);
    cudaGetSymbolAddress((void**)&xhi,  g_xhi);
    cudaGetSymbolAddress((void**)&xlo,  g_xlo);
    cudaGetSymbolAddress((void**)&wahi, g_Wahi);
    cudaGetSymbolAddress((void**)&walo, g_Walo);
    cudaGetSymbolAddress((void**)&wphi, g_Wphi);
    cudaGetSymbolAddress((void**)&wplo, g_Wplo);
    cudaGetSymbolAddress((void**)&yhi,  g_yhi);
    cudaGetSymbolAddress((void**)&ylo,  g_ylo);

    cudaFuncSetAttribute(attn_kernel,
                         cudaFuncAttributeMaxDynamicSharedMemorySize, ATTN_SMEM);
    cudaFuncSetAttribute(hmma_gemm,
                         cudaFuncAttributeMaxDynamicSharedMemorySize, GEMM_SMEM);

    t_kernel<<<1, 1024>>>(tok);
    split_kernel<<<(M_ALL*Cn/4 + 255)/256, 256>>>(x,  xhi,  xlo,  M_ALL*Cn/4);
    split_kernel<<<(Cn*N_QKV/4 + 255)/256, 256>>>(Wa, wahi, walo, Cn*N_QKV/4);
    split_kernel<<<(Cn*Cn/4 + 255)/256, 256>>>(Wp, wphi, wplo, Cn*Cn/4);

    hmma_gemm<<<dim3(N_QKV/128, M_ALL/128), 256, GEMM_SMEM>>>(
        xhi, xlo, wahi, walo, qkv_p, M_ALL, N_QKV, Cn);

    transform_kernel<<<(Bn*Tn*Hn*64)/256, 256>>>(cum);
    attn_kernel<<<dim3(Tn/64, Bn*Hn), 128, ATTN_SMEM>>>(padm);

    split_kernel<<<(M_ALL*Cn/4 + 255)/256, 256>>>(y_p, yhi, ylo, M_ALL*Cn/4);
    hmma_gemm<<<dim3(Cn/128, M_ALL/128), 256, GEMM_SMEM>>>(
        yhi, ylo, wphi, wplo, out, M_ALL, Cn, Cn);
}

// round 4
// speedup vs baseline: 2.8075x; 1.3752x over previous
#include <cuda_runtime.h>
#include <cuda_bf16.h>
#include <cstdint>
#include <math.h>

#define Bn   4
#define Tn   1024
#define Cn   2048
#define Hn   16
#define HDn  128
#define NBLK 1024
#define M_ALL (Bn*Tn)          // 4096
#define N_QKV (3*Cn)           // 6144

// ---------------- scratch (device globals; no runtime allocation) -------------
__device__ float g_qkv[(size_t)M_ALL * N_QKV];      // 100.7 MB
__device__ float g_t[Bn*Tn];
// bf16 split scratch
__device__ __nv_bfloat16 g_xhi[(size_t)M_ALL*Cn],  g_xlo[(size_t)M_ALL*Cn];
__device__ __nv_bfloat16 g_Wahi[(size_t)Cn*N_QKV], g_Walo[(size_t)Cn*N_QKV];
__device__ __nv_bfloat16 g_Wphi[(size_t)Cn*Cn],    g_Wplo[(size_t)Cn*Cn];
__device__ __nv_bfloat16 g_yhi[(size_t)M_ALL*Cn],  g_ylo[(size_t)M_ALL*Cn];
// q/k/v bf16 splits, layout [B*H][T][HD]
#define QKV_ELEMS ((size_t)Bn*Hn*Tn*HDn)
__device__ __nv_bfloat16 g_qh[QKV_ELEMS], g_ql[QKV_ELEMS];
__device__ __nv_bfloat16 g_kh[QKV_ELEMS], g_kl[QKV_ELEMS];
__device__ __nv_bfloat16 g_vh[QKV_ELEMS], g_vl[QKV_ELEMS];

__device__ __forceinline__ uint32_t smem_u32(const void* p) {
    uint32_t a;
    asm("{ .reg .u64 t; cvta.to.shared.u64 t, %1; cvt.u32.u64 %0, t; }"
        : "=r"(a) : "l"(p));
    return a;
}
#define CP_ASYNC16(sa, gp) \
    asm volatile("cp.async.cg.shared.global [%0], [%1], 16;" :: "r"(sa), "l"(gp))
#define CP_COMMIT() asm volatile("cp.async.commit_group;" ::: "memory")
#define CP_WAIT(n)  asm volatile("cp.async.wait_group %0;" :: "n"(n) : "memory")

#define LDSM4(f, ad) \
    asm volatile("ldmatrix.sync.aligned.m8n8.x4.shared.b16 {%0,%1,%2,%3}, [%4];" \
        : "=r"((f)[0]), "=r"((f)[1]), "=r"((f)[2]), "=r"((f)[3]) : "r"(ad))
#define LDSM4T(f, ad) \
    asm volatile("ldmatrix.sync.aligned.m8n8.x4.trans.shared.b16 {%0,%1,%2,%3}, [%4];" \
        : "=r"((f)[0]), "=r"((f)[1]), "=r"((f)[2]), "=r"((f)[3]) : "r"(ad))
#define MMA(cp, a, b0, b1) \
    asm volatile("mma.sync.aligned.m16n8k16.row.col.f32.bf16.bf16.f32 " \
        "{%0,%1,%2,%3}, {%4,%5,%6,%7}, {%8,%9}, {%0,%1,%2,%3};" \
        : "+f"((cp)[0]), "+f"((cp)[1]), "+f"((cp)[2]), "+f"((cp)[3]) \
        : "r"((a)[0]), "r"((a)[1]), "r"((a)[2]), "r"((a)[3]), "r"(b0), "r"(b1))

__device__ __forceinline__ void pack_hl(float x, float y, uint32_t& hi, uint32_t& lo) {
    asm("cvt.rn.bf16x2.f32 %0, %1, %2;" : "=r"(hi) : "f"(y), "f"(x));
    float xl = x - __uint_as_float(hi << 16);
    float yl = y - __uint_as_float(hi & 0xFFFF0000u);
    asm("cvt.rn.bf16x2.f32 %0, %1, %2;" : "=r"(lo) : "f"(yl), "f"(xl));
}

// ---------------- split kernel: f32 -> bf16 hi + bf16 lo ----------------------
__global__ void split_kernel(const float* __restrict__ src,
                             __nv_bfloat16* __restrict__ hi,
                             __nv_bfloat16* __restrict__ lo, int n4) {
    int i = blockIdx.x * blockDim.x + threadIdx.x;
    if (i >= n4) return;
    float4 v = ((const float4*)src)[i];
    float xs[4] = {v.x, v.y, v.z, v.w};
    __nv_bfloat16 h[4], l[4];
    #pragma unroll
    for (int j = 0; j < 4; j++) {
        h[j] = __float2bfloat16_rn(xs[j]);
        l[j] = __float2bfloat16_rn(xs[j] - __bfloat162float(h[j]));
    }
    ((uint2*)hi)[i] = *(uint2*)h;
    ((uint2*)lo)[i] = *(uint2*)l;
}

// ==================== HMMA bf16-split GEMM (from R3, unchanged) ===============
#define ST_BYTES 32768
#define OFF_AL   8192
#define OFF_BH   16384
#define OFF_BL   24576
#define GEMM_SMEM (4*ST_BYTES)

__device__ __forceinline__ void issue_stage(
        const __nv_bfloat16* __restrict__ Ah, const __nv_bfloat16* __restrict__ Al,
        const __nv_bfloat16* __restrict__ Bh, const __nv_bfloat16* __restrict__ Bl,
        int K, int N, int m0, int n0, int k0, uint32_t st, int tid) {
    #pragma unroll
    for (int i = 0; i < 2; i++) {
        int g = tid + i*256;               // 0..511
        int m = g >> 2, c = g & 3;         // A: 128 rows x 4 chunks(16B)
        size_t ga = (size_t)(m0 + m)*K + k0 + c*8;
        uint32_t sa = st + m*64 + (((uint32_t)c ^ ((m>>1)&3)) << 4);
        CP_ASYNC16(sa,          Ah + ga);
        CP_ASYNC16(sa + OFF_AL, Al + ga);
        int k = g >> 4, cn = g & 15;       // B: 32 rows x 16 chunks
        size_t gb = (size_t)(k0 + k)*N + n0 + cn*8;
        uint32_t sb = st + OFF_BH + k*256 + (((uint32_t)cn ^ (k&7)) << 4);
        CP_ASYNC16(sb,          Bh + gb);
        CP_ASYNC16(sb + 8192,   Bl + gb);
    }
}

__device__ __forceinline__ void ldm_a(uint32_t base, int rowbase, int s,
                                      uint32_t* f, int lane) {
    int row = rowbase + (lane & 7) + 8*((lane>>3)&1);
    int ch  = 2*s + (lane>>4);
    uint32_t a = base + row*64 + (((uint32_t)ch ^ ((row>>1)&3)) << 4);
    LDSM4(f, a);
}
__device__ __forceinline__ void ldm_b(uint32_t base, int s, int cb,
                                      uint32_t* f, int lane) {
    int k  = 16*s + (lane & 7) + 8*((lane>>3)&1);
    int ch = cb + (lane>>4);
    uint32_t a = base + k*256 + (((uint32_t)ch ^ (k&7)) << 4);
    LDSM4T(f, a);
}

__global__ __launch_bounds__(256, 1)
void hmma_gemm(const __nv_bfloat16* __restrict__ Ah, const __nv_bfloat16* __restrict__ Al,
               const __nv_bfloat16* __restrict__ Bh, const __nv_bfloat16* __restrict__ Bl,
               float* __restrict__ Cg, int M, int N, int K) {
    extern __shared__ char smraw[];
    uint32_t sb = smem_u32(smraw);
    int tid = threadIdx.x;
    int lane = tid & 31, warp = tid >> 5;
    int wm = warp >> 2, wn = warp & 3;
    int m0 = blockIdx.y * 128, n0 = blockIdx.x * 128;

    float acc[4][4][4];
    #pragma unroll
    for (int a = 0; a < 4; a++)
        #pragma unroll
        for (int b = 0; b < 4; b++)
            #pragma unroll
            for (int c = 0; c < 4; c++) acc[a][b][c] = 0.0f;

    const int NK = K / 32;
    #pragma unroll
    for (int p = 0; p < 3; p++) {
        issue_stage(Ah, Al, Bh, Bl, K, N, m0, n0, p*32, sb + p*ST_BYTES, tid);
        CP_COMMIT();
    }

    for (int kt = 0; kt < NK; kt++) {
        CP_WAIT(2);
        __syncthreads();
        uint32_t st = sb + (kt & 3)*ST_BYTES;
        #pragma unroll
        for (int s = 0; s < 2; s++) {
            uint32_t af[4][4], alf[4][4], bf[2][4], blf[2][4];
            #pragma unroll
            for (int mi = 0; mi < 4; mi++) {
                ldm_a(st,          wm*64 + mi*16, s, af[mi],  lane);
                ldm_a(st + OFF_AL, wm*64 + mi*16, s, alf[mi], lane);
            }
            #pragma unroll
            for (int nj = 0; nj < 2; nj++) {
                ldm_b(st + OFF_BH, s, wn*4 + nj*2, bf[nj],  lane);
                ldm_b(st + OFF_BL, s, wn*4 + nj*2, blf[nj], lane);
            }
            #pragma unroll
            for (int mi = 0; mi < 4; mi++)
                #pragma unroll
                for (int ni = 0; ni < 4; ni++) {
                    int nj = ni >> 1, o = (ni & 1) << 1;
                    MMA(acc[mi][ni], af[mi],  bf[nj][o],  bf[nj][o+1]);
                    MMA(acc[mi][ni], af[mi],  blf[nj][o], blf[nj][o+1]);
                    MMA(acc[mi][ni], alf[mi], bf[nj][o],  bf[nj][o+1]);
                }
        }
        if (kt + 3 < NK)
            issue_stage(Ah, Al, Bh, Bl, K, N, m0, n0, (kt+3)*32,
                        sb + ((kt+3) & 3)*ST_BYTES, tid);
        CP_COMMIT();
    }

    int rq = lane >> 2, cq = (lane & 3) << 1;
    #pragma unroll
    for (int mi = 0; mi < 4; mi++) {
        int r = m0 + wm*64 + mi*16 + rq;
        #pragma unroll
        for (int ni = 0; ni < 4; ni++) {
            int cc = n0 + wn*32 + ni*8 + cq;
            *(float2*)&Cg[(size_t)r*N + cc] =
                make_float2(acc[mi][ni][0], acc[mi][ni][1]);
            *(float2*)&Cg[(size_t)(r+8)*N + cc] =
                make_float2(acc[mi][ni][2], acc[mi][ni][3]);
        }
    }
}

// ---------------- kernel 1: global histogram + per-batch cumsum ---------------
__global__ void t_kernel(const int* __restrict__ tok) {
    __shared__ int   cnt[NBLK];
    __shared__ float buf[Tn];
    int tid = threadIdx.x;
    cnt[tid] = 0;
    __syncthreads();
    for (int i = tid; i < Bn*Tn; i += blockDim.x)
        atomicAdd(&cnt[tok[i]], 1);
    __syncthreads();
    for (int b = 0; b < Bn; b++) {
        float r = 1.0f / ((float)cnt[tok[b*Tn + tid]] + 1e-10f);
        buf[tid] = r;
        __syncthreads();
        #pragma unroll
        for (int off = 1; off < Tn; off <<= 1) {
            float v = (tid >= off) ? buf[tid - off] : 0.0f;
            __syncthreads();
            buf[tid] += v;
            __syncthreads();
        }
        g_t[b*Tn + tid] = buf[tid];
        __syncthreads();
    }
}

// ---------------- kernel 3: RoPE + overrides, emit bf16 hi/lo q/k/v ----------
__global__ void transform_kernel(const float* __restrict__ cum) {
    int idx = blockIdx.x * blockDim.x + threadIdx.x;
    int j = idx & 63;
    int h = (idx >> 6) & (Hn-1);
    int t = (idx >> 10) & (Tn-1);
    int b = idx >> 20;

    const float* row = g_qkv + (size_t)(b*Tn + t) * N_QKV;
    float tv = g_t[b*Tn + t];
    float invf = (float)exp(-(double)j * (9.210340371976184 / 64.0));
    float ang = tv * invf;
    float sn, cs_;
    sincosf(ang, &sn, &cs_);

    float q1 = row[h*HDn + j],        q2 = row[h*HDn + j + 64];
    float k1 = row[Cn + h*HDn + j],   k2 = row[Cn + h*HDn + j + 64];
    float v1 = row[2*Cn + h*HDn + j], v2 = row[2*Cn + h*HDn + j + 64];
    float cscore = cum[b*Tn + t];
    float ev = expf(cscore);

    float qo1 = q1*cs_ - q2*sn, qo2 = q2*cs_ + q1*sn;
    float ko1 = k1*cs_ - k2*sn, ko2 = k2*cs_ + k1*sn;
    if (j == 63) { qo2 = 1.0f; ko2 = cscore; }
    float vo1 = v1*ev, vo2 = v2*ev;

    size_t base = (((size_t)(b*Hn + h))*Tn + t) * HDn;
    #pragma unroll
    for (int p = 0; p < 3; p++) {
        float a = (p==0) ? qo1 : (p==1) ? ko1 : vo1;
        float c = (p==0) ? qo2 : (p==1) ? ko2 : vo2;
        __nv_bfloat16* dh = (p==0) ? g_qh : (p==1) ? g_kh : g_vh;
        __nv_bfloat16* dl = (p==0) ? g_ql : (p==1) ? g_kl : g_vl;
        __nv_bfloat16 ah = __float2bfloat16_rn(a);
        __nv_bfloat16 ch = __float2bfloat16_rn(c);
        dh[base + j]      = ah;
        dh[base + j + 64] = ch;
        dl[base + j]      = __float2bfloat16_rn(a - __bfloat162float(ah));
        dl[base + j + 64] = __float2bfloat16_rn(c - __bfloat162float(ch));
    }
}

// ---------------- kernel 4: flash attention, HMMA bf16-split -----------------
// 64 q-rows/CTA, 4 warps x 16 rows, 64-key tiles, double-buffered K/V.
// smem: Qh 16K | Ql 16K | 2 x (Kh,Kl,Vh,Vl 16K each) | 2 x pads 256B
#define A_QH   0
#define A_QL   16384
#define A_BUF  32768
#define A_PADS (32768 + 131072)
#define ATTN_SMEM (A_PADS + 512)
#define SCALE_A 0.08838834764831843f
#define NEG_A  -1.0e30f

__device__ __forceinline__ void attn_load_tile(uint32_t sb, int buf, int bh,
                                               int b, int kb,
                                               const int* __restrict__ pad,
                                               int tid) {
    uint32_t base = sb + A_BUF + buf*65536;
    #pragma unroll
    for (int i = 0; i < 8; i++) {
        int g = tid + i*128;
        int row = g >> 4, ch = g & 15;
        size_t off = ((size_t)bh*Tn + kb + row)*HDn + ch*8;
        uint32_t sw = row*256 + (((uint32_t)(ch ^ (row & 7))) << 4);
        CP_ASYNC16(base + sw,         g_kh + off);
        CP_ASYNC16(base + 16384 + sw, g_kl + off);
        CP_ASYNC16(base + 32768 + sw, g_vh + off);
        CP_ASYNC16(base + 49152 + sw, g_vl + off);
    }
    if (tid < 16)
        CP_ASYNC16(sb + A_PADS + buf*256 + tid*16, pad + b*Tn + kb + tid*4);
}

__global__ __launch_bounds__(128, 1)
void attn_hmma(const int* __restrict__ pad) {
    extern __shared__ char smraw[];
    uint32_t sb = smem_u32(smraw);
    int tid = threadIdx.x, lane = tid & 31, w = tid >> 5;
    int mtile = blockIdx.x, bh = blockIdx.y;
    int b = bh >> 4, h = bh & 15;
    int q0 = mtile*64;

    // load Q tile (hi/lo)
    #pragma unroll
    for (int i = 0; i < 8; i++) {
        int g = tid + i*128;
        int row = g >> 4, ch = g & 15;
        size_t off = ((size_t)bh*Tn + q0 + row)*HDn + ch*8;
        uint32_t sw = row*256 + (((uint32_t)(ch ^ (row & 7))) << 4);
        CP_ASYNC16(sb + A_QH + sw, g_qh + off);
        CP_ASYNC16(sb + A_QL + sw, g_ql + off);
    }
    attn_load_tile(sb, 0, bh, b, 0, pad, tid);
    CP_COMMIT();

    float o[16][4];
    #pragma unroll
    for (int nt = 0; nt < 16; nt++)
        #pragma unroll
        for (int e = 0; e < 4; e++) o[nt][e] = 0.0f;
    float m0f = -3.0e38f, m1f = -3.0e38f, l0f = 0.0f, l1f = 0.0f;

    int rq = lane >> 2, cq2 = (lane & 3) << 1;
    int qg0 = q0 + w*16 + rq, qg1 = qg0 + 8;

    for (int n = 0; n <= mtile; n++) {
        int cur = n & 1;
        if (n < mtile) {
            attn_load_tile(sb, cur ^ 1, bh, b, (n+1)*64, pad, tid);
            CP_COMMIT();
            CP_WAIT(1);
        } else {
            CP_WAIT(0);
        }
        __syncthreads();

        uint32_t bufb = sb + A_BUF + cur*65536;
        int kb = n*64;

        // ---- S = Q K^T, 3-term split
        float sa[8][4];
        #pragma unroll
        for (int nt = 0; nt < 8; nt++)
            #pragma unroll
            for (int e = 0; e < 4; e++) sa[nt][e] = 0.0f;

        #pragma unroll
        for (int s = 0; s < 8; s++) {
            uint32_t qhf[4], qlf[4];
            {
                int row = w*16 + (lane & 7) + 8*((lane>>3)&1);
                int ch  = 2*s + (lane>>4);
                uint32_t ad = sb + A_QH + row*256 +
                              (((uint32_t)(ch ^ (row & 7))) << 4);
                LDSM4(qhf, ad);
                LDSM4(qlf, ad + 16384);
            }
            #pragma unroll
            for (int g4 = 0; g4 < 4; g4++) {
                uint32_t khf[4], klf[4];
                int key = g4*16 + (lane & 7) + 8*((lane>>3)&1);
                int ch  = 2*s + (lane>>4);
                uint32_t ad = bufb + key*256 +
                              (((uint32_t)(ch ^ (key & 7))) << 4);
                LDSM4(khf, ad);
                LDSM4(klf, ad + 16384);
                MMA(sa[2*g4],   qhf, khf[0], khf[2]);
                MMA(sa[2*g4],   qhf, klf[0], klf[2]);
                MMA(sa[2*g4],   qlf, khf[0], khf[2]);
                MMA(sa[2*g4+1], qhf, khf[1], khf[3]);
                MMA(sa[2*g4+1], qhf, klf[1], klf[3]);
                MMA(sa[2*g4+1], qlf, khf[1], khf[3]);
            }
        }

        // ---- scale + mask
        const int* padp = (const int*)(smraw + (A_PADS - 0) + cur*256);
        #pragma unroll
        for (int nt = 0; nt < 8; nt++) {
            int kc = nt*8 + cq2;
            int kg = kb + kc;
            int p0 = padp[kc], p1 = padp[kc+1];
            float v;
            v = sa[nt][0]*SCALE_A; if (kg   > qg0 || !p0) v = NEG_A; sa[nt][0] = v;
            v = sa[nt][1]*SCALE_A; if (kg+1 > qg0 || !p1) v = NEG_A; sa[nt][1] = v;
            v = sa[nt][2]*SCALE_A; if (kg   > qg1 || !p0) v = NEG_A; sa[nt][2] = v;
            v = sa[nt][3]*SCALE_A; if (kg+1 > qg1 || !p1) v = NEG_A; sa[nt][3] = v;
        }

        // ---- online softmax (rows rq and rq+8)
        float mx0 = -3.0e38f, mx1 = -3.0e38f;
        #pragma unroll
        for (int nt = 0; nt < 8; nt++) {
            mx0 = fmaxf(mx0, fmaxf(sa[nt][0], sa[nt][1]));
            mx1 = fmaxf(mx1, fmaxf(sa[nt][2], sa[nt][3]));
        }
        mx0 = fmaxf(mx0, __shfl_xor_sync(0xffffffffu, mx0, 1));
        mx0 = fmaxf(mx0, __shfl_xor_sync(0xffffffffu, mx0, 2));
        mx1 = fmaxf(mx1, __shfl_xor_sync(0xffffffffu, mx1, 1));
        mx1 = fmaxf(mx1, __shfl_xor_sync(0xffffffffu, mx1, 2));
        float mn0 = fmaxf(m0f, mx0), mn1 = fmaxf(m1f, mx1);
        float al0 = __expf(m0f - mn0), al1 = __expf(m1f - mn1);
        m0f = mn0; m1f = mn1;
        float s0 = 0.0f, s1 = 0.0f;
        #pragma unroll
        for (int nt = 0; nt < 8; nt++) {
            sa[nt][0] = __expf(sa[nt][0] - mn0); s0 += sa[nt][0];
            sa[nt][1] = __expf(sa[nt][1] - mn0); s0 += sa[nt][1];
            sa[nt][2] = __expf(sa[nt][2] - mn1); s1 += sa[nt][2];
            sa[nt][3] = __expf(sa[nt][3] - mn1); s1 += sa[nt][3];
        }
        s0 += __shfl_xor_sync(0xffffffffu, s0, 1);
        s0 += __shfl_xor_sync(0xffffffffu, s0, 2);
        s1 += __shfl_xor_sync(0xffffffffu, s1, 1);
        s1 += __shfl_xor_sync(0xffffffffu, s1, 2);
        l0f = l0f*al0 + s0;
        l1f = l1f*al1 + s1;
        #pragma unroll
        for (int nt = 0; nt < 16; nt++) {
            o[nt][0] *= al0; o[nt][1] *= al0;
            o[nt][2] *= al1; o[nt][3] *= al1;
        }

        // ---- O += P V, 3-term split (P split in registers)
        #pragma unroll
        for (int j = 0; j < 4; j++) {
            uint32_t aph[4], apl[4];
            pack_hl(sa[2*j][0],   sa[2*j][1],   aph[0], apl[0]);
            pack_hl(sa[2*j][2],   sa[2*j][3],   aph[1], apl[1]);
            pack_hl(sa[2*j+1][0], sa[2*j+1][1], aph[2], apl[2]);
            pack_hl(sa[2*j+1][2], sa[2*j+1][3], aph[3], apl[3]);
            #pragma unroll
            for (int u = 0; u < 8; u++) {
                uint32_t vhf[4], vlf[4];
                int key = j*16 + (lane & 7) + 8*((lane>>3)&1);
                int ch  = u*2 + (lane>>4);
                uint32_t ad = bufb + 32768 + key*256 +
                              (((uint32_t)(ch ^ (key & 7))) << 4);
                LDSM4T(vhf, ad);
                LDSM4T(vlf, ad + 16384);
                MMA(o[2*u],   aph, vhf[0], vhf[1]);
                MMA(o[2*u],   aph, vlf[0], vlf[1]);
                MMA(o[2*u],   apl, vhf[0], vhf[1]);
                MMA(o[2*u+1], aph, vhf[2], vhf[3]);
                MMA(o[2*u+1], aph, vlf[2], vlf[3]);
                MMA(o[2*u+1], apl, vhf[2], vhf[3]);
            }
        }
        __syncthreads();   // protect buffer before next prefetch overwrites it
    }

    // ---- epilogue: normalize, split to bf16 hi/lo, write y[B,T,C]
    float i0 = 1.0f / l0f, i1 = 1.0f / l1f;
    size_t r0g = (size_t)(b*Tn + q0 + w*16 + rq)*Cn + h*HDn;
    size_t r1g = r0g + (size_t)8*Cn;
    #pragma unroll
    for (int nt = 0; nt < 16; nt++) {
        int col = nt*8 + cq2;
        uint32_t hi, lo;
        pack_hl(o[nt][0]*i0, o[nt][1]*i0, hi, lo);
        ((uint32_t*)g_yhi)[(r0g + col) >> 1] = hi;
        ((uint32_t*)g_ylo)[(r0g + col) >> 1] = lo;
        pack_hl(o[nt][2]*i1, o[nt][3]*i1, hi, lo);
        ((uint32_t*)g_yhi)[(r1g + col) >> 1] = hi;
        ((uint32_t*)g_ylo)[(r1g + col) >> 1] = lo;
    }
}

// ---------------- launcher ----------------------------------------------------
extern "C" void kernel_launch(void* const* d_in, const int* in_sizes, int n_in,
                              void* d_out, int out_size) {
    const float* x    = (const float*)d_in[0];
    const float* cum  = (const float*)d_in[1];
    const int*   tok  = (const int*)d_in[2];
    const int*   padm = (const int*)d_in[3];
    const float* Wa   = (const float*)d_in[4];
    const float* Wp   = (const float*)d_in[5];
    float* out = (float*)d_out;

    float *qkv_p;
    __nv_bfloat16 *xhi, *xlo, *wahi, *walo, *wphi, *wplo, *yhi, *ylo;
    cudaGetSymbolAddress((void**)&qkv_p, g_qkv);
    cudaGetSymbolAddress((void**)&xhi,  g_xhi);
    cudaGetSymbolAddress((void**)&xlo,  g_xlo);
    cudaGetSymbolAddress((void**)&wahi, g_Wahi);
    cudaGetSymbolAddress((void**)&walo, g_Walo);
    cudaGetSymbolAddress((void**)&wphi, g_Wphi);
    cudaGetSymbolAddress((void**)&wplo, g_Wplo);
    cudaGetSymbolAddress((void**)&yhi,  g_yhi);
    cudaGetSymbolAddress((void**)&ylo,  g_ylo);

    cudaFuncSetAttribute(attn_hmma,
                         cudaFuncAttributeMaxDynamicSharedMemorySize, ATTN_SMEM);
    cudaFuncSetAttribute(hmma_gemm,
                         cudaFuncAttributeMaxDynamicSharedMemorySize, GEMM_SMEM);

    t_kernel<<<1, 1024>>>(tok);
    split_kernel<<<(M_ALL*Cn/4 + 255)/256, 256>>>(x,  xhi,  xlo,  M_ALL*Cn/4);
    split_kernel<<<(Cn*N_QKV/4 + 255)/256, 256>>>(Wa, wahi, walo, Cn*N_QKV/4);
    split_kernel<<<(Cn*Cn/4 + 255)/256, 256>>>(Wp, wphi, wplo, Cn*Cn/4);

    hmma_gemm<<<dim3(N_QKV/128, M_ALL/128), 256, GEMM_SMEM>>>(
        xhi, xlo, wahi, walo, qkv_p, M_ALL, N_QKV, Cn);

    transform_kernel<<<(Bn*Tn*Hn*64)/256, 256>>>(cum);
    attn_hmma<<<dim3(Tn/64, Bn*Hn), 128, ATTN_SMEM>>>(padm);

    hmma_gemm<<<dim3(Cn/128, M_ALL/128), 256, GEMM_SMEM>>>(
        yhi, ylo, wphi, wplo, out, M_ALL, Cn, Cn);
}